// round 5
// baseline (speedup 1.0000x reference)
#include <cuda_runtime.h>
#include <math.h>

// ---------------- problem constants ----------------
namespace cfg {
constexpr int B   = 4;
constexpr int S   = 2048;
constexpr int D   = 2048;
constexpr int NH  = 16;
constexpr int NKV = 4;
constexpr int HD  = 128;
constexpr int NREP = NH / NKV;           // 4
constexpr int NTOT = D + 2 * NKV * HD;   // 3072 (Q | K | V output columns)
}
using namespace cfg;

// ---------------- scratch (static device globals; no allocation) ----------------
__device__ float g_Q[(size_t)B * NH  * S * HD];   // [b,h,s,hd]   67 MB
__device__ float g_K[(size_t)B * NKV * S * HD];   // [b,kh,s,hd]  16.8 MB
__device__ float g_V[(size_t)B * NKV * S * HD];   // [b,kh,s,hd]  16.8 MB

// =====================================================================
// Kernel 1: fused QKV projection GEMM.
//   out[m, n] = sum_d x[m, d] * W[n, d]   (x @ W^T)
//   m = b*S + s in [0, 8192);  n in [0, 3072): [0,2048)=Q, [2048,2560)=K, rest V
//   Results scattered directly into [b, head, s, hd] layouts.
// 128x128x16 tiles, 256 threads, 8x8 per thread, reg-prefetch single buffer.
// =====================================================================
constexpr int GBM = 128, GBN = 128, GBK = 16, GLD = GBM + 4;

__global__ __launch_bounds__(256, 2)
void qkv_gemm_kernel(const float* __restrict__ x,
                     const float* __restrict__ wq,
                     const float* __restrict__ wk,
                     const float* __restrict__ wv)
{
    __shared__ __align__(16) float As[GBK * GLD];
    __shared__ __align__(16) float Bs[GBK * GLD];

    const int tid = threadIdx.x;
    const int tx = tid & 15, ty = tid >> 4;
    const int m0 = blockIdx.x * GBM;
    const int nt = blockIdx.y * GBN;

    // Whole 128-wide N tile lies inside exactly one weight matrix and one head.
    const float* W;
    int which, head;
    if (nt < D)                  { W = wq + (size_t)nt * D;                  which = 0; head = nt / HD; }
    else if (nt < D + NKV * HD)  { W = wk + (size_t)(nt - D) * D;            which = 1; head = (nt - D) / HD; }
    else                         { W = wv + (size_t)(nt - D - NKV * HD) * D; which = 2; head = (nt - D - NKV * HD) / HD; }

    const float* Ax = x + (size_t)m0 * D;

    float acc[8][8];
    #pragma unroll
    for (int i = 0; i < 8; i++)
        #pragma unroll
        for (int j = 0; j < 8; j++) acc[i][j] = 0.f;

    const int r0 = tid >> 2,          c0 = tid & 3;          // rows 0..63
    const int r1 = (tid + 256) >> 2,  c1 = (tid + 256) & 3;  // rows 64..127

    float4 aP0, aP1, bP0, bP1;

    auto fetch = [&](int kk) {
        aP0 = *(const float4*)(Ax + (size_t)r0 * D + kk + c0 * 4);
        aP1 = *(const float4*)(Ax + (size_t)r1 * D + kk + c1 * 4);
        bP0 = *(const float4*)(W  + (size_t)r0 * D + kk + c0 * 4);
        bP1 = *(const float4*)(W  + (size_t)r1 * D + kk + c1 * 4);
    };
    auto store_smem = [&]() {
        As[(c0 * 4 + 0) * GLD + r0] = aP0.x; As[(c0 * 4 + 1) * GLD + r0] = aP0.y;
        As[(c0 * 4 + 2) * GLD + r0] = aP0.z; As[(c0 * 4 + 3) * GLD + r0] = aP0.w;
        As[(c1 * 4 + 0) * GLD + r1] = aP1.x; As[(c1 * 4 + 1) * GLD + r1] = aP1.y;
        As[(c1 * 4 + 2) * GLD + r1] = aP1.z; As[(c1 * 4 + 3) * GLD + r1] = aP1.w;
        Bs[(c0 * 4 + 0) * GLD + r0] = bP0.x; Bs[(c0 * 4 + 1) * GLD + r0] = bP0.y;
        Bs[(c0 * 4 + 2) * GLD + r0] = bP0.z; Bs[(c0 * 4 + 3) * GLD + r0] = bP0.w;
        Bs[(c1 * 4 + 0) * GLD + r1] = bP1.x; Bs[(c1 * 4 + 1) * GLD + r1] = bP1.y;
        Bs[(c1 * 4 + 2) * GLD + r1] = bP1.z; Bs[(c1 * 4 + 3) * GLD + r1] = bP1.w;
    };

    fetch(0);
    store_smem();

    constexpr int KTILES = D / GBK;   // 128
    #pragma unroll 1
    for (int t = 0; t < KTILES; ++t) {
        __syncthreads();
        if (t + 1 < KTILES) fetch((t + 1) * GBK);  // overlap gmem with compute

        #pragma unroll
        for (int kb = 0; kb < GBK; kb++) {
            const float4 a0 = *(const float4*)&As[kb * GLD + ty * 8];
            const float4 a1 = *(const float4*)&As[kb * GLD + ty * 8 + 4];
            const float4 b0 = *(const float4*)&Bs[kb * GLD + tx * 8];
            const float4 b1 = *(const float4*)&Bs[kb * GLD + tx * 8 + 4];
            const float a[8] = {a0.x, a0.y, a0.z, a0.w, a1.x, a1.y, a1.z, a1.w};
            const float b[8] = {b0.x, b0.y, b0.z, b0.w, b1.x, b1.y, b1.z, b1.w};
            #pragma unroll
            for (int i = 0; i < 8; i++)
                #pragma unroll
                for (int j = 0; j < 8; j++)
                    acc[i][j] = fmaf(a[i], b[j], acc[i][j]);
        }
        __syncthreads();
        if (t + 1 < KTILES) store_smem();
    }

    // scatter epilogue into [b, head, s, hd]
    float* dst;
    int nhx;
    if (which == 0)      { dst = g_Q; nhx = NH;  }
    else if (which == 1) { dst = g_K; nhx = NKV; }
    else                 { dst = g_V; nhx = NKV; }

    #pragma unroll
    for (int i = 0; i < 8; i++) {
        const int m  = m0 + ty * 8 + i;
        const int bb = m / S, ss = m % S;
        float* drow = dst + (((size_t)bb * nhx + head) * S + ss) * HD + tx * 8;
        float4 v0 = {acc[i][0], acc[i][1], acc[i][2], acc[i][3]};
        float4 v1 = {acc[i][4], acc[i][5], acc[i][6], acc[i][7]};
        *(float4*)(drow)     = v0;
        *(float4*)(drow + 4) = v1;
    }
}

// =====================================================================
// Kernel 2: RoPE in place on Q (isQ=1) or K (isQ=0).
//   out[i]    = t[i]*cos[i]    - t[i+64]*sin[i]        (i < 64)
//   out[i+64] = t[i+64]*cos[i+64] + t[i]*sin[i+64]
// =====================================================================
__global__ void rope_kernel(const float* __restrict__ cosp,
                            const float* __restrict__ sinp, int isQ)
{
    const int total = (isQ ? B * NH : B * NKV) * S * 64;
    const int idx = blockIdx.x * blockDim.x + threadIdx.x;
    if (idx >= total) return;

    const int i  = idx & 63;
    const int s  = (idx >> 6) & (S - 1);
    const int bh = idx >> 17;                 // 64 * 2048 = 2^17

    float* row = (isQ ? g_Q : g_K) + ((size_t)bh * S + s) * HD;
    const float lo = row[i], hi = row[i + 64];
    const float cl = cosp[s * HD + i],      sl = sinp[s * HD + i];
    const float ch = cosp[s * HD + i + 64], sh = sinp[s * HD + i + 64];
    row[i]      = lo * cl - hi * sl;
    row[i + 64] = hi * ch + lo * sh;
}

// =====================================================================
// Kernel 3: causal flash attention with GQA.
// One block per (q-tile of 64, h, b). 256 threads as 16x16.
// Each thread: 4 score rows (ty), 4 score cols / 8 output cols (tx).
// smem row pads chosen for conflict-free access:
//   Qs/Ks rows padded to 129 floats (scalar loads, bank = (c + k) % 32),
//   Vs rows padded to 132 floats (aligned float4 loads),
//   Ps rows padded to 65 floats (broadcast reads).
// =====================================================================
constexpr int ABM = 64, ABN = 64;
constexpr int QLD = 129, KLD = 129, VLD = 132, PLD = 65;
constexpr int SMQ  = ABM * QLD;
constexpr int SMKV = ABN * VLD;       // >= ABN*KLD
constexpr int SMP  = ABM * PLD;
constexpr int ATTN_SMEM_BYTES = (SMQ + SMKV + SMP) * (int)sizeof(float); // 83456

__global__ __launch_bounds__(256)
void attn_kernel(float* __restrict__ out)
{
    extern __shared__ __align__(16) float sm[];
    float* Qs  = sm;
    float* KVs = sm + SMQ;
    float* Ps  = KVs + SMKV;

    const int tid = threadIdx.x;
    const int tx = tid & 15, ty = tid >> 4;
    const int m0 = blockIdx.x * ABM;
    const int h  = blockIdx.y;
    const int b  = blockIdx.z;
    const int kh = h / NREP;

    const float* Qg = g_Q + ((size_t)(b * NH  + h ) * S) * HD;
    const float* Kg = g_K + ((size_t)(b * NKV + kh) * S) * HD;
    const float* Vg = g_V + ((size_t)(b * NKV + kh) * S) * HD;

    // load Q tile [64 x 128]
    for (int i = tid; i < ABM * HD / 4; i += 256) {
        const int r = i >> 5;
        const int k = (i & 31) * 4;
        const float4 v = *(const float4*)(Qg + (size_t)(m0 + r) * HD + k);
        Qs[r * QLD + k + 0] = v.x; Qs[r * QLD + k + 1] = v.y;
        Qs[r * QLD + k + 2] = v.z; Qs[r * QLD + k + 3] = v.w;
    }

    float Oacc[4][8];
    #pragma unroll
    for (int a = 0; a < 4; a++)
        #pragma unroll
        for (int j = 0; j < 8; j++) Oacc[a][j] = 0.f;
    float mrow[4], lrow[4];
    #pragma unroll
    for (int a = 0; a < 4; a++) { mrow[a] = -1e30f; lrow[a] = 0.f; }

    const float SCALE = 0.0883883476483184f;  // 1/sqrt(128)
    const int jt = m0 / ABN;                  // last (diagonal) kv tile index

    #pragma unroll 1
    for (int j = 0; j <= jt; ++j) {
        const int n0 = j * ABN;
        __syncthreads();   // prior PV done reading KVs/Ps; Q visible after next sync
        // load K tile [64 x 128] with 129-pad
        for (int i = tid; i < ABN * HD / 4; i += 256) {
            const int r = i >> 5;
            const int k = (i & 31) * 4;
            const float4 v = *(const float4*)(Kg + (size_t)(n0 + r) * HD + k);
            KVs[r * KLD + k + 0] = v.x; KVs[r * KLD + k + 1] = v.y;
            KVs[r * KLD + k + 2] = v.z; KVs[r * KLD + k + 3] = v.w;
        }
        __syncthreads();

        // S = Q K^T  (4x4 per thread; cols c = tx + 16*cb -> conflict-free)
        float sreg[4][4];
        #pragma unroll
        for (int a = 0; a < 4; a++)
            #pragma unroll
            for (int cb = 0; cb < 4; cb++) sreg[a][cb] = 0.f;

        #pragma unroll 4
        for (int k = 0; k < HD; k++) {
            float av[4], bv[4];
            #pragma unroll
            for (int a = 0; a < 4; a++)  av[a]  = Qs[(ty * 4 + a) * QLD + k];
            #pragma unroll
            for (int cb = 0; cb < 4; cb++) bv[cb] = KVs[(tx + 16 * cb) * KLD + k];
            #pragma unroll
            for (int a = 0; a < 4; a++)
                #pragma unroll
                for (int cb = 0; cb < 4; cb++)
                    sreg[a][cb] = fmaf(av[a], bv[cb], sreg[a][cb]);
        }

        // scale + causal mask (only the diagonal tile needs masking)
        const bool diag = (j == jt);
        #pragma unroll
        for (int a = 0; a < 4; a++) {
            const int qr = ty * 4 + a;
            #pragma unroll
            for (int cb = 0; cb < 4; cb++) {
                const int c = tx + 16 * cb;
                float sv = sreg[a][cb] * SCALE;
                if (diag && c > qr) sv = -1e30f;
                sreg[a][cb] = sv;
            }
        }

        // streaming softmax update (row reduction over the 16 tx lanes)
        #pragma unroll
        for (int a = 0; a < 4; a++) {
            float tm = fmaxf(fmaxf(sreg[a][0], sreg[a][1]), fmaxf(sreg[a][2], sreg[a][3]));
            #pragma unroll
            for (int off = 8; off; off >>= 1)
                tm = fmaxf(tm, __shfl_xor_sync(0xffffffffu, tm, off));
            const float mnew  = fmaxf(mrow[a], tm);
            const float alpha = __expf(mrow[a] - mnew);
            mrow[a] = mnew;
            float ps = 0.f;
            #pragma unroll
            for (int cb = 0; cb < 4; cb++) {
                const float p = __expf(sreg[a][cb] - mnew);
                sreg[a][cb] = p;
                ps += p;
            }
            #pragma unroll
            for (int off = 8; off; off >>= 1)
                ps += __shfl_xor_sync(0xffffffffu, ps, off);
            lrow[a] = lrow[a] * alpha + ps;
            #pragma unroll
            for (int jj = 0; jj < 8; jj++) Oacc[a][jj] *= alpha;
            #pragma unroll
            for (int cb = 0; cb < 4; cb++)
                Ps[(ty * 4 + a) * PLD + tx + 16 * cb] = sreg[a][cb];
        }
        __syncthreads();   // P visible; K reads finished -> safe to overwrite with V

        // load V tile [64 x 128] with 132-pad (float4 aligned)
        for (int i = tid; i < ABN * HD / 4; i += 256) {
            const int r = i >> 5;
            const int k = (i & 31) * 4;
            *(float4*)&KVs[r * VLD + k] =
                *(const float4*)(Vg + (size_t)(n0 + r) * HD + k);
        }
        __syncthreads();

        // O += P V   (4 rows x 8 cols per thread)
        #pragma unroll 2
        for (int c = 0; c < ABN; c++) {
            float p[4];
            #pragma unroll
            for (int a = 0; a < 4; a++) p[a] = Ps[(ty * 4 + a) * PLD + c];
            const float4 v0 = *(const float4*)&KVs[c * VLD + tx * 8];
            const float4 v1 = *(const float4*)&KVs[c * VLD + tx * 8 + 4];
            const float vv[8] = {v0.x, v0.y, v0.z, v0.w, v1.x, v1.y, v1.z, v1.w};
            #pragma unroll
            for (int a = 0; a < 4; a++)
                #pragma unroll
                for (int jj = 0; jj < 8; jj++)
                    Oacc[a][jj] = fmaf(p[a], vv[jj], Oacc[a][jj]);
        }
    }

    // normalize and write out[b, s, h*HD + hd]
    #pragma unroll
    for (int a = 0; a < 4; a++) {
        const int qr = m0 + ty * 4 + a;
        const float inv = 1.f / lrow[a];
        float* drow = out + ((size_t)b * S + qr) * D + h * HD + tx * 8;
        float4 o0 = {Oacc[a][0] * inv, Oacc[a][1] * inv, Oacc[a][2] * inv, Oacc[a][3] * inv};
        float4 o1 = {Oacc[a][4] * inv, Oacc[a][5] * inv, Oacc[a][6] * inv, Oacc[a][7] * inv};
        *(float4*)(drow)     = o0;
        *(float4*)(drow + 4) = o1;
    }
}

// =====================================================================
// launch
// =====================================================================
extern "C" void kernel_launch(void* const* d_in, const int* in_sizes, int n_in,
                              void* d_out, int out_size)
{
    const float* x    = (const float*)d_in[0];
    const float* cosp = (const float*)d_in[1];
    const float* sinp = (const float*)d_in[2];
    const float* wq   = (const float*)d_in[3];
    const float* wk   = (const float*)d_in[4];
    const float* wv   = (const float*)d_in[5];
    // d_in[6] = start_pos (always 0 in this problem)
    float* out = (float*)d_out;

    // 1) QKV projections
    dim3 ggrid(B * S / GBM, NTOT / GBN);   // (64, 24)
    qkv_gemm_kernel<<<ggrid, 256>>>(x, wq, wk, wv);

    // 2) RoPE on Q and K
    {
        const int totQ = B * NH * S * 64;
        rope_kernel<<<(totQ + 255) / 256, 256>>>(cosp, sinp, 1);
        const int totK = B * NKV * S * 64;
        rope_kernel<<<(totK + 255) / 256, 256>>>(cosp, sinp, 0);
    }

    // 3) causal flash attention (dynamic smem > 48KB)
    cudaFuncSetAttribute(attn_kernel,
                         cudaFuncAttributeMaxDynamicSharedMemorySize,
                         ATTN_SMEM_BYTES);
    attn_kernel<<<dim3(S / ABM, NH, B), 256, ATTN_SMEM_BYTES>>>(out);
}

// round 15
// speedup vs baseline: 2.7425x; 2.7425x over previous
#include <cuda_runtime.h>
#include <math.h>

// ---------------- problem constants ----------------
namespace cfg {
constexpr int B   = 4;
constexpr int S   = 2048;
constexpr int D   = 2048;
constexpr int NH  = 16;
constexpr int NKV = 4;
constexpr int HD  = 128;
constexpr int NREP = NH / NKV;           // 4
constexpr int NTOT = D + 2 * NKV * HD;   // 3072
}
using namespace cfg;

// ---------------- scratch ----------------
__device__ float g_Q[(size_t)B * NH  * S * HD];
__device__ float g_K[(size_t)B * NKV * S * HD];
__device__ float g_V[(size_t)B * NKV * S * HD];

// =====================================================================
// tf32 helpers
// =====================================================================
__device__ __forceinline__ unsigned f2tf32(float x) {
    unsigned y;
    asm("cvt.rna.tf32.f32 %0, %1;" : "=r"(y) : "f"(x));
    return y;
}

__device__ __forceinline__ void mma_tf32(float c[4], const unsigned a[4], const unsigned b[2]) {
    asm volatile(
        "mma.sync.aligned.m16n8k8.row.col.f32.tf32.tf32.f32 "
        "{%0,%1,%2,%3}, {%4,%5,%6,%7}, {%8,%9}, {%0,%1,%2,%3};\n"
        : "+f"(c[0]), "+f"(c[1]), "+f"(c[2]), "+f"(c[3])
        : "r"(a[0]), "r"(a[1]), "r"(a[2]), "r"(a[3]),
          "r"(b[0]), "r"(b[1]));
}

// =====================================================================
// Kernel 1: fused QKV projection GEMM on tensor cores (tf32 mma.sync).
// (unchanged from the audited Round-5 candidate)
// =====================================================================
constexpr int TBM = 128, TBN = 64, TBK = 32;
constexpr int APITCH = 36;

__global__ __launch_bounds__(256)
void qkv_gemm_tc(const float* __restrict__ x,
                 const float* __restrict__ wq,
                 const float* __restrict__ wk,
                 const float* __restrict__ wv)
{
    __shared__ __align__(16) unsigned As[TBM * APITCH];
    __shared__ __align__(16) unsigned Bs[TBN * APITCH];

    const int tid  = threadIdx.x;
    const int lane = tid & 31;
    const int w    = tid >> 5;
    const int wM   = w >> 2;
    const int wN   = w & 3;
    const int r    = lane >> 2;
    const int kk   = lane & 3;

    const int m0  = blockIdx.x * TBM;
    const int nt0 = blockIdx.y * TBN;

    const float* W;
    float* dst;
    int nhx, off;
    if (nt0 < D)                 { W = wq + (size_t)nt0 * D;                  dst = g_Q; nhx = NH;  off = nt0; }
    else if (nt0 < D + NKV * HD) { W = wk + (size_t)(nt0 - D) * D;            dst = g_K; nhx = NKV; off = nt0 - D; }
    else                         { W = wv + (size_t)(nt0 - D - NKV * HD) * D; dst = g_V; nhx = NKV; off = nt0 - D - NKV * HD; }

    const float* Ax = x + (size_t)m0 * D;

    float cf[4][2][4];
    #pragma unroll
    for (int mt = 0; mt < 4; mt++)
        #pragma unroll
        for (int nt = 0; nt < 2; nt++)
            #pragma unroll
            for (int i = 0; i < 4; i++) cf[mt][nt][i] = 0.f;

    const int ldr = tid >> 3;
    const int kq  = tid & 7;

    float4 aF[4], bF[2];

    auto fetch = [&](int k0) {
        #pragma unroll
        for (int p = 0; p < 4; p++)
            aF[p] = *(const float4*)(Ax + (size_t)(ldr + p * 32) * D + k0 + kq * 4);
        #pragma unroll
        for (int p = 0; p < 2; p++)
            bF[p] = *(const float4*)(W + (size_t)(ldr + p * 32) * D + k0 + kq * 4);
    };
    auto store_smem = [&]() {
        #pragma unroll
        for (int p = 0; p < 4; p++) {
            uint4 t = {f2tf32(aF[p].x), f2tf32(aF[p].y), f2tf32(aF[p].z), f2tf32(aF[p].w)};
            *(uint4*)&As[(ldr + p * 32) * APITCH + kq * 4] = t;
        }
        #pragma unroll
        for (int p = 0; p < 2; p++) {
            uint4 t = {f2tf32(bF[p].x), f2tf32(bF[p].y), f2tf32(bF[p].z), f2tf32(bF[p].w)};
            *(uint4*)&Bs[(ldr + p * 32) * APITCH + kq * 4] = t;
        }
    };

    fetch(0);
    store_smem();

    constexpr int KTILES = D / TBK;
    #pragma unroll 1
    for (int t = 0; t < KTILES; ++t) {
        __syncthreads();
        if (t + 1 < KTILES) fetch((t + 1) * TBK);

        #pragma unroll
        for (int ks = 0; ks < 4; ks++) {
            const int kb = ks * 8;
            unsigned af[4][4], bf[2][2];
            #pragma unroll
            for (int mt = 0; mt < 4; mt++) {
                const int row = wM * 64 + mt * 16 + r;
                af[mt][0] = As[row * APITCH + kb + kk];
                af[mt][1] = As[(row + 8) * APITCH + kb + kk];
                af[mt][2] = As[row * APITCH + kb + kk + 4];
                af[mt][3] = As[(row + 8) * APITCH + kb + kk + 4];
            }
            #pragma unroll
            for (int nt = 0; nt < 2; nt++) {
                const int col = wN * 16 + nt * 8 + r;
                bf[nt][0] = Bs[col * APITCH + kb + kk];
                bf[nt][1] = Bs[col * APITCH + kb + kk + 4];
            }
            #pragma unroll
            for (int mt = 0; mt < 4; mt++)
                #pragma unroll
                for (int nt = 0; nt < 2; nt++)
                    mma_tf32(cf[mt][nt], af[mt], bf[nt]);
        }

        __syncthreads();
        if (t + 1 < KTILES) store_smem();
    }

    #pragma unroll
    for (int mt = 0; mt < 4; mt++) {
        #pragma unroll
        for (int h2 = 0; h2 < 2; h2++) {
            const int gm = m0 + wM * 64 + mt * 16 + r + h2 * 8;
            const int bb = gm >> 11;
            const int ss = gm & 2047;
            #pragma unroll
            for (int nt = 0; nt < 2; nt++) {
                const int ncol = off + wN * 16 + nt * 8 + 2 * kk;
                const int head = ncol >> 7;
                const int hd   = ncol & 127;
                float2 v = {cf[mt][nt][h2 * 2], cf[mt][nt][h2 * 2 + 1]};
                *(float2*)(dst + (((size_t)bb * nhx + head) * S + ss) * HD + hd) = v;
            }
        }
    }
}

// =====================================================================
// Kernel 2: RoPE in place (unchanged).
// =====================================================================
__global__ void rope_kernel(const float* __restrict__ cosp,
                            const float* __restrict__ sinp, int isQ)
{
    const int total = (isQ ? B * NH : B * NKV) * S * 64;
    const int idx = blockIdx.x * blockDim.x + threadIdx.x;
    if (idx >= total) return;

    const int i  = idx & 63;
    const int s  = (idx >> 6) & (S - 1);
    const int bh = idx >> 17;

    float* row = (isQ ? g_Q : g_K) + ((size_t)bh * S + s) * HD;
    const float lo = row[i], hi = row[i + 64];
    const float cl = cosp[s * HD + i],      sl = sinp[s * HD + i];
    const float ch = cosp[s * HD + i + 64], sh = sinp[s * HD + i + 64];
    row[i]      = lo * cl - hi * sl;
    row[i + 64] = hi * ch + lo * sh;
}

// =====================================================================
// Kernel 3: causal flash attention, BOTH GEMMs on tensor cores (tf32).
// Block: 256 threads = 8 warps; each warp owns a 16-row Q strip (ATM=128).
// KV tile ATN=64. Lane (r=lane>>2, kk=lane&3) owns score/O rows r,r+8 of
// its strip and cols 2kk,2kk+1 per 8-wide n-tile (m16n8k8 C layout).
// P is passed QK->PV via smem round-trip (C-store then A-frag load).
// V is stored transposed ([hd][seq]) so it can serve as the col-major B.
// All smem pitches are ≡4 (mod 32) words => frag-access bank = lane id.
// =====================================================================
constexpr int ATM = 128, ATN = 64;
constexpr int QP = 132, KP = 132, VP = 68, PP = 68;
constexpr int SM_QS  = 0;
constexpr int SM_KVS = ATM * QP;                 // 16896
constexpr int SM_PS  = SM_KVS + ATM * VP;        // 16896 + 8704 = 25600
constexpr int ATTN_SMEM_WORDS = SM_PS + ATM * PP;          // 34304
constexpr int ATTN_SMEM_BYTES = ATTN_SMEM_WORDS * 4;       // 137216

__global__ __launch_bounds__(256, 1)
void attn_tc(float* __restrict__ out)
{
    extern __shared__ __align__(16) unsigned sm[];
    unsigned* Qs  = sm + SM_QS;     // [128][132] tf32
    unsigned* KVs = sm + SM_KVS;    // K: [64][132] tf32 ; then V^T: [128][68]
    unsigned* Ps  = sm + SM_PS;     // [128][68] tf32

    const int tid  = threadIdx.x;
    const int lane = tid & 31;
    const int w    = tid >> 5;
    const int r    = lane >> 2;
    const int kk   = lane & 3;
    const int W0   = w * 16;

    const int m0 = blockIdx.x * ATM;
    const int h  = blockIdx.y;
    const int b  = blockIdx.z;
    const int kh = h / NREP;

    const float* Qg = g_Q + ((size_t)(b * NH  + h ) * S) * HD;
    const float* Kg = g_K + ((size_t)(b * NKV + kh) * S) * HD;
    const float* Vg = g_V + ((size_t)(b * NKV + kh) * S) * HD;

    // Q tile -> smem (tf32), [row][k] pitch 132
    for (int i = tid; i < ATM * HD / 4; i += 256) {
        const int row = i >> 5;
        const int k4  = (i & 31) * 4;
        const float4 v = *(const float4*)(Qg + (size_t)(m0 + row) * HD + k4);
        uint4 t = {f2tf32(v.x), f2tf32(v.y), f2tf32(v.z), f2tf32(v.w)};
        *(uint4*)&Qs[row * QP + k4] = t;
    }

    float O[16][4];
    #pragma unroll
    for (int nt = 0; nt < 16; nt++)
        #pragma unroll
        for (int e = 0; e < 4; e++) O[nt][e] = 0.f;

    float m_lo = -1e30f, m_hi = -1e30f, l_lo = 0.f, l_hi = 0.f;
    const float SCALE = 0.0883883476483184f;  // 1/sqrt(128)
    const int row_lo = m0 + W0 + r;
    const int row_hi = row_lo + 8;

    const int jt = (m0 + ATM - 1) / ATN;      // 2*bx + 1

    #pragma unroll 1
    for (int j = 0; j <= jt; ++j) {
        const int n0 = j * ATN;
        __syncthreads();   // prev PV done with KVs/Ps; Q visible after next sync
        // K tile -> smem (tf32), [n][k] pitch 132
        for (int i = tid; i < ATN * HD / 4; i += 256) {
            const int row = i >> 5;
            const int k4  = (i & 31) * 4;
            const float4 v = *(const float4*)(Kg + (size_t)(n0 + row) * HD + k4);
            uint4 t = {f2tf32(v.x), f2tf32(v.y), f2tf32(v.z), f2tf32(v.w)};
            *(uint4*)&KVs[row * KP + k4] = t;
        }
        __syncthreads();

        // ---- S = Q K^T via mma (per warp: 16 x 64, k=128) ----
        float s[8][4];
        #pragma unroll
        for (int nt = 0; nt < 8; nt++)
            #pragma unroll
            for (int e = 0; e < 4; e++) s[nt][e] = 0.f;

        #pragma unroll
        for (int ks = 0; ks < 16; ks++) {
            const int kb = ks * 8;
            unsigned a[4];
            a[0] = Qs[(W0 + r)     * QP + kb + kk];
            a[1] = Qs[(W0 + r + 8) * QP + kb + kk];
            a[2] = Qs[(W0 + r)     * QP + kb + kk + 4];
            a[3] = Qs[(W0 + r + 8) * QP + kb + kk + 4];
            #pragma unroll
            for (int nt = 0; nt < 8; nt++) {
                unsigned bb2[2] = {KVs[(nt * 8 + r) * KP + kb + kk],
                                   KVs[(nt * 8 + r) * KP + kb + kk + 4]};
                mma_tf32(s[nt], a, bb2);
            }
        }

        // ---- scale + causal mask ----
        #pragma unroll
        for (int nt = 0; nt < 8; nt++) {
            const int c0 = n0 + nt * 8 + 2 * kk;
            float sv;
            sv = s[nt][0] * SCALE; if (c0     > row_lo) sv = -1e30f; s[nt][0] = sv;
            sv = s[nt][1] * SCALE; if (c0 + 1 > row_lo) sv = -1e30f; s[nt][1] = sv;
            sv = s[nt][2] * SCALE; if (c0     > row_hi) sv = -1e30f; s[nt][2] = sv;
            sv = s[nt][3] * SCALE; if (c0 + 1 > row_hi) sv = -1e30f; s[nt][3] = sv;
        }

        // ---- streaming softmax (rows owned by quad lanes) ----
        float mt_lo = -1e30f, mt_hi = -1e30f;
        #pragma unroll
        for (int nt = 0; nt < 8; nt++) {
            mt_lo = fmaxf(mt_lo, fmaxf(s[nt][0], s[nt][1]));
            mt_hi = fmaxf(mt_hi, fmaxf(s[nt][2], s[nt][3]));
        }
        mt_lo = fmaxf(mt_lo, __shfl_xor_sync(0xffffffffu, mt_lo, 1));
        mt_lo = fmaxf(mt_lo, __shfl_xor_sync(0xffffffffu, mt_lo, 2));
        mt_hi = fmaxf(mt_hi, __shfl_xor_sync(0xffffffffu, mt_hi, 1));
        mt_hi = fmaxf(mt_hi, __shfl_xor_sync(0xffffffffu, mt_hi, 2));

        const float mn_lo = fmaxf(m_lo, mt_lo);
        const float mn_hi = fmaxf(m_hi, mt_hi);
        const float alo = __expf(m_lo - mn_lo);
        const float ahi = __expf(m_hi - mn_hi);
        m_lo = mn_lo; m_hi = mn_hi;

        float ps_lo = 0.f, ps_hi = 0.f;
        #pragma unroll
        for (int nt = 0; nt < 8; nt++) {
            const float p0 = __expf(s[nt][0] - mn_lo);
            const float p1 = __expf(s[nt][1] - mn_lo);
            const float p2 = __expf(s[nt][2] - mn_hi);
            const float p3 = __expf(s[nt][3] - mn_hi);
            ps_lo += p0 + p1;
            ps_hi += p2 + p3;
            uint2 t0 = {f2tf32(p0), f2tf32(p1)};
            uint2 t1 = {f2tf32(p2), f2tf32(p3)};
            *(uint2*)&Ps[(W0 + r)     * PP + nt * 8 + 2 * kk] = t0;
            *(uint2*)&Ps[(W0 + r + 8) * PP + nt * 8 + 2 * kk] = t1;
        }
        ps_lo += __shfl_xor_sync(0xffffffffu, ps_lo, 1);
        ps_lo += __shfl_xor_sync(0xffffffffu, ps_lo, 2);
        ps_hi += __shfl_xor_sync(0xffffffffu, ps_hi, 1);
        ps_hi += __shfl_xor_sync(0xffffffffu, ps_hi, 2);
        l_lo = l_lo * alo + ps_lo;
        l_hi = l_hi * ahi + ps_hi;

        #pragma unroll
        for (int nt = 0; nt < 16; nt++) {
            O[nt][0] *= alo; O[nt][1] *= alo;
            O[nt][2] *= ahi; O[nt][3] *= ahi;
        }
        __syncthreads();   // all warps done reading K tile

        // V tile -> smem TRANSPOSED (tf32): V^T [hd][c] pitch 68
        for (int i = tid; i < ATN * HD / 4; i += 256) {
            const int c  = i & 63;
            const int h0 = (i >> 6) * 4;
            const float4 v = *(const float4*)(Vg + (size_t)(n0 + c) * HD + h0);
            KVs[(h0 + 0) * VP + c] = f2tf32(v.x);
            KVs[(h0 + 1) * VP + c] = f2tf32(v.y);
            KVs[(h0 + 2) * VP + c] = f2tf32(v.z);
            KVs[(h0 + 3) * VP + c] = f2tf32(v.w);
        }
        __syncthreads();

        // ---- O += P V via mma (per warp: 16 x 128, k=64) ----
        #pragma unroll
        for (int cs = 0; cs < 8; cs++) {
            const int cb = cs * 8;
            unsigned a[4];
            a[0] = Ps[(W0 + r)     * PP + cb + kk];
            a[1] = Ps[(W0 + r + 8) * PP + cb + kk];
            a[2] = Ps[(W0 + r)     * PP + cb + kk + 4];
            a[3] = Ps[(W0 + r + 8) * PP + cb + kk + 4];
            #pragma unroll
            for (int nt = 0; nt < 16; nt++) {
                unsigned bb2[2] = {KVs[(nt * 8 + r) * VP + cb + kk],
                                   KVs[(nt * 8 + r) * VP + cb + kk + 4]};
                mma_tf32(O[nt], a, bb2);
            }
        }
    }

    // ---- normalize + write out[b, s, h*HD + hd] ----
    const float il_lo = 1.f / l_lo;
    const float il_hi = 1.f / l_hi;
    float* o_lo = out + ((size_t)b * S + row_lo) * D + h * HD;
    float* o_hi = o_lo + (size_t)8 * D;
    #pragma unroll
    for (int nt = 0; nt < 16; nt++) {
        float2 v0 = {O[nt][0] * il_lo, O[nt][1] * il_lo};
        float2 v1 = {O[nt][2] * il_hi, O[nt][3] * il_hi};
        *(float2*)(o_lo + nt * 8 + 2 * kk) = v0;
        *(float2*)(o_hi + nt * 8 + 2 * kk) = v1;
    }
}

// =====================================================================
// launch
// =====================================================================
extern "C" void kernel_launch(void* const* d_in, const int* in_sizes, int n_in,
                              void* d_out, int out_size)
{
    const float* x    = (const float*)d_in[0];
    const float* cosp = (const float*)d_in[1];
    const float* sinp = (const float*)d_in[2];
    const float* wq   = (const float*)d_in[3];
    const float* wk   = (const float*)d_in[4];
    const float* wv   = (const float*)d_in[5];
    float* out = (float*)d_out;

    // 1) QKV projections on tensor cores (tf32)
    dim3 ggrid(B * S / TBM, NTOT / TBN);   // (64, 48)
    qkv_gemm_tc<<<ggrid, 256>>>(x, wq, wk, wv);

    // 2) RoPE on Q and K
    {
        const int totQ = B * NH * S * 64;
        rope_kernel<<<(totQ + 255) / 256, 256>>>(cosp, sinp, 1);
        const int totK = B * NKV * S * 64;
        rope_kernel<<<(totK + 255) / 256, 256>>>(cosp, sinp, 0);
    }

    // 3) causal flash attention on tensor cores (tf32)
    cudaFuncSetAttribute(attn_tc,
                         cudaFuncAttributeMaxDynamicSharedMemorySize,
                         ATTN_SMEM_BYTES);
    attn_tc<<<dim3(S / ATM, NH, B), 256, ATTN_SMEM_BYTES>>>(out);
}